// round 17
// baseline (speedup 1.0000x reference)
#include <cuda_runtime.h>
#include <cuda_fp16.h>
#include <cstdint>
#include <cmath>

#define BB 64
#define SS 1024
#define DD 768

// ---------------------------------------------------------------------------
// Scratch (__device__ globals; no cudaMalloc allowed)
// ---------------------------------------------------------------------------
__device__ __half g_Hhi[(size_t)BB * SS * DD];   // 96 MB
__device__ __half g_Phi[(size_t)BB * SS * DD];   // 96 MB
__device__ __half g_Mhi[DD * DD];
__device__ float  g_q[BB * SS];
__device__ unsigned g_ctr;                       // work-claim counter
__device__ int g_done[BB * 8];                   // per (b, row-block) mm1 completion

// ---------------------------------------------------------------------------
// Helpers (baseline PTX only: cp.async / ldmatrix / mma.sync — no 'a' features)
// ---------------------------------------------------------------------------
__device__ __forceinline__ uint32_t smem_u32(const void* p) {
    return (uint32_t)__cvta_generic_to_shared(p);
}

__device__ __forceinline__ void cpasync16(uint32_t s, const void* g) {
    asm volatile("cp.async.cg.shared.global [%0], [%1], 16;" :: "r"(s), "l"(g) : "memory");
}

__device__ __forceinline__ void ldm4(uint32_t& r0, uint32_t& r1, uint32_t& r2, uint32_t& r3,
                                     uint32_t a) {
    asm volatile("ldmatrix.sync.aligned.m8n8.x4.shared.b16 {%0,%1,%2,%3}, [%4];"
                 : "=r"(r0), "=r"(r1), "=r"(r2), "=r"(r3) : "r"(a));
}

__device__ __forceinline__ void mma16816(float* d, const uint32_t* a, const uint32_t* b) {
    asm volatile("mma.sync.aligned.m16n8k16.row.col.f32.f16.f16.f32 "
                 "{%0,%1,%2,%3}, {%4,%5,%6,%7}, {%8,%9}, {%0,%1,%2,%3};"
                 : "+f"(d[0]), "+f"(d[1]), "+f"(d[2]), "+f"(d[3])
                 : "r"(a[0]), "r"(a[1]), "r"(a[2]), "r"(a[3]), "r"(b[0]), "r"(b[1]));
}

// ---------------------------------------------------------------------------
// Merged conversion kernel: blocks [0, NB_CONV) convert batch -> Hhi (fp16),
// tail blocks build Mh = fl16(proj + proj^T), zero g_q / g_done / g_ctr.
// ---------------------------------------------------------------------------
#define NB_CONV ((int)(((size_t)BB * SS * DD / 4) / 256))   // 49152
#define NB_PREP ((DD * DD + 255) / 256)                     // 2304

__global__ void k_conv(const float* __restrict__ batch, const float* __restrict__ proj) {
    if (blockIdx.x < NB_CONV) {
        size_t i = ((size_t)blockIdx.x * 256 + threadIdx.x) * 4;
        float4 v = *(const float4*)(batch + i);
        __half2 a, b;
        a.x = __float2half_rn(v.x); a.y = __float2half_rn(v.y);
        b.x = __float2half_rn(v.z); b.y = __float2half_rn(v.w);
        ((__half2*)(g_Hhi + i))[0] = a;
        ((__half2*)(g_Hhi + i))[1] = b;
    } else {
        int idx = (blockIdx.x - NB_CONV) * 256 + threadIdx.x;
        if (idx < DD * DD) {
            int i = idx / DD, j = idx % DD;
            g_Mhi[idx] = __float2half_rn(proj[idx] + proj[j * DD + i]);
        }
        if (idx < BB * SS) g_q[idx] = 0.0f;     // zero q accumulator each launch
        if (idx < BB * 8)  g_done[idx] = 0;     // zero completion flags
        if (idx == 0)      g_ctr = 0u;          // zero work counter
    }
}

// ---------------------------------------------------------------------------
// Persistent fused GEMM worker. Work items claimed off g_ctr:
//   [0, 3072)    : mm1 tile  D = Hhi.Mh^T  -> Phi + q atomics; publishes
//                  g_done[b*8+y] after a fence.
//   [3072, 5376) : mm2 tile (triangular bi>=bj)  D = Phi.Hhi^T -> out with
//                  q_i+q_j-D epilogue + smem-transpose mirror. Spin-waits on
//                  g_done of its two row-blocks (6 panels each).
// Deadlock-free: counter order claims all mm1 items before any mm2 item;
// mm1 never blocks; every claimed item is processed by a resident CTA.
// Engine: R16 shape — 256 thr, 2x4 warps, 64x32 warp tiles, BK=64 (128B rows,
// SW128 swizzle), NSTAGE=3 (96KB), 2 CTAs/SM.
// ---------------------------------------------------------------------------
#define BM 128
#define BN 128
#define BK 64
#define NSTAGE 3
#define TILE_BYTES 16384                     // 128 rows x 128B
#define STAGE_B (2 * TILE_BYTES)             // 32768
#define KITERS (DD / BK)                     // 12
#define TPAD 132
#define SMEM_MM (NSTAGE * STAGE_B)           // 98304 (>= 128*TPAD*4 = 67584)
#define ITEMS1 (6 * 8 * BB)                  // 3072 mm1 tiles
#define ITEMS2 (36 * BB)                     // 2304 mm2 tiles
#define TOTAL  (ITEMS1 + ITEMS2)             // 5376
#define GRID_W 304                           // 2 per SM (152 SMs); extras exit

// smem tile layout: row r (128B), chunk c (16B, 0..7), swizzle c ^= r&7
__device__ __forceinline__ void load_tile(uint32_t s, const __half* g, int kt, int tid) {
    #pragma unroll
    for (int i = 0; i < 4; i++) {
        int id = tid + i * 256;                 // 0..1023
        int r  = id >> 3;                       // 0..127
        int c  = id & 7;                        // 0..7
        const char* gp = (const char*)g + (size_t)r * (DD * 2) + (size_t)kt * 128 + c * 16;
        uint32_t sa = s + r * 128 + ((c ^ (r & 7)) << 4);
        cpasync16(sa, gp);
    }
}

__global__ void __launch_bounds__(256, 2) k_work(float* __restrict__ out,
                                                 const float* __restrict__ batch) {
    extern __shared__ char smem[];
    const uint32_t sb = smem_u32(smem);
    __shared__ unsigned s_item;

    const int tid = threadIdx.x, lane = tid & 31, wid = tid >> 5;
    const int wm = wid & 1;        // warp M index (0..1), tile 64 rows
    const int wn = wid >> 1;       // warp N index (0..3), tile 32 cols

    // ldmatrix per-lane addressing (item-invariant; 128B rows, swizzle = r&7)
    const int g8 = lane >> 3, r8 = lane & 7;
    uint32_t aRB[4];  int aSW[4];
    #pragma unroll
    for (int i = 0; i < 4; i++) {
        int r = wm * 64 + i * 16 + r8 + (g8 & 1) * 8;
        aRB[i] = (uint32_t)r * 128;
        aSW[i] = r & 7;
    }
    const int aCB = g8 >> 1;
    uint32_t bRB[2];  int bSW[2];
    #pragma unroll
    for (int j = 0; j < 2; j++) {
        int r = wn * 32 + j * 16 + r8 + (g8 >> 1) * 8;
        bRB[j] = (uint32_t)r * 128;
        bSW[j] = r & 7;
    }
    const int bCB = g8 & 1;

    for (;;) {
        __syncthreads();                       // protect smem from previous item
        if (tid == 0) s_item = atomicAdd(&g_ctr, 1u);
        __syncthreads();
        const unsigned item = s_item;
        if (item >= TOTAL) return;

        const bool epi = item >= ITEMS1;
        int b, y = 0, bi = 0, bj = 0, rowA0, rowB0;
        const __half *pA, *pB;
        if (!epi) {
            int x = item % 6;                  // x fastest: 6 items reuse A in L2
            y = (item / 6) % 8;
            b = item / 48;
            rowA0 = y * BM;
            rowB0 = x * BN;
            pA = g_Hhi + (size_t)b * SS * DD + (size_t)rowA0 * DD;
            pB = g_Mhi + (size_t)rowB0 * DD;   // M symmetric: row j == col j
        } else {
            int t   = item - ITEMS1;
            int tri = t % 36;                  // tri fastest: 36 items share batch b
            b = t / 36;
            bi = (int)((sqrtf(8.f * tri + 1.f) - 1.f) * 0.5f);
            while ((bi + 1) * (bi + 2) / 2 <= tri) bi++;
            while (bi * (bi + 1) / 2 > tri) bi--;
            bj = tri - bi * (bi + 1) / 2;
            rowA0 = bi * BM;
            rowB0 = bj * BN;
            pA = g_Phi + (size_t)b * SS * DD + (size_t)rowA0 * DD;
            pB = g_Hhi + (size_t)b * SS * DD + (size_t)rowB0 * DD;
            // Wait for the 6 mm1 panels of each needed row-block (P rows + q).
            if (tid == 0) {
                while (atomicAdd(&g_done[b * 8 + bi], 0) < 6) __nanosleep(64);
                while (atomicAdd(&g_done[b * 8 + bj], 0) < 6) __nanosleep(64);
                __threadfence();               // acquire
            }
            __syncthreads();
        }

        float acc[4][4][4] = {};

        // Prologue: stages 0..NSTAGE-2
        #pragma unroll
        for (int s = 0; s < NSTAGE - 1; s++) {
            uint32_t st = sb + (uint32_t)s * STAGE_B;
            load_tile(st,              pA, s, tid);
            load_tile(st + TILE_BYTES, pB, s, tid);
            asm volatile("cp.async.commit_group;" ::: "memory");
        }

        #pragma unroll 1
        for (int kt = 0; kt < KITERS; kt++) {
            if (kt < KITERS - 1) asm volatile("cp.async.wait_group 1;" ::: "memory");
            else                 asm volatile("cp.async.wait_group 0;" ::: "memory");
            __syncthreads();

            if (kt + NSTAGE - 1 < KITERS) {
                uint32_t st = sb + (uint32_t)((kt + NSTAGE - 1) % NSTAGE) * STAGE_B;
                int kn = kt + NSTAGE - 1;
                load_tile(st,              pA, kn, tid);
                load_tile(st + TILE_BYTES, pB, kn, tid);
                asm volatile("cp.async.commit_group;" ::: "memory");
            }

            const uint32_t st = sb + (uint32_t)(kt % NSTAGE) * STAGE_B;
            #pragma unroll
            for (int ks = 0; ks < 4; ks++) {
                uint32_t ah[4][4], bh[2][4];
                #pragma unroll
                for (int i = 0; i < 4; i++) {
                    uint32_t off = aRB[i] + (uint32_t)(((aCB + ks * 2) ^ aSW[i]) << 4);
                    ldm4(ah[i][0], ah[i][1], ah[i][2], ah[i][3], st + off);
                }
                #pragma unroll
                for (int j = 0; j < 2; j++) {
                    uint32_t off = bRB[j] + (uint32_t)(((bCB + ks * 2) ^ bSW[j]) << 4);
                    ldm4(bh[j][0], bh[j][1], bh[j][2], bh[j][3], st + TILE_BYTES + off);
                }
                #pragma unroll
                for (int i = 0; i < 4; i++)
                    #pragma unroll
                    for (int j = 0; j < 4; j++)
                        mma16816(acc[i][j], ah[i], &bh[j >> 1][(j & 1) * 2]);
            }
        }

        // ------------------------------ Epilogue ---------------------------
        const int mrow = rowA0 + wm * 64 + lane / 4;       // +i*16, +8
        const int ncol = rowB0 + wn * 32 + (lane % 4) * 2; // +j*8

        if (!epi) {
            __half* dh = g_Phi + (size_t)b * SS * DD;
            const float* Hb = batch + (size_t)b * SS * DD;
            #pragma unroll
            for (int i = 0; i < 4; i++)
                #pragma unroll
                for (int j = 0; j < 4; j++) {
                    int r0 = mrow + i * 16, c = ncol + j * 8;
                    #pragma unroll
                    for (int h = 0; h < 2; h++) {
                        int r = r0 + h * 8;
                        __half2 hh;
                        hh.x = __float2half_rn(acc[i][j][2 * h + 0]);
                        hh.y = __float2half_rn(acc[i][j][2 * h + 1]);
                        *(__half2*)(dh + (size_t)r * DD + c) = hh;
                    }
                }
            // Fused q: q[b,r] += 0.5 * sum_c P[r,c] * H[r,c] over this panel
            #pragma unroll
            for (int i = 0; i < 4; i++)
                #pragma unroll
                for (int h = 0; h < 2; h++) {
                    int r = mrow + i * 16 + h * 8;
                    float p = 0.f;
                    #pragma unroll
                    for (int j = 0; j < 4; j++) {
                        int c = ncol + j * 8;
                        float2 hv = *(const float2*)(Hb + (size_t)r * DD + c);
                        p += acc[i][j][2 * h + 0] * hv.x + acc[i][j][2 * h + 1] * hv.y;
                    }
                    p += __shfl_xor_sync(0xFFFFFFFFu, p, 1);
                    p += __shfl_xor_sync(0xFFFFFFFFu, p, 2);
                    if ((lane & 3) == 0)
                        atomicAdd(&g_q[(size_t)b * SS + r], 0.5f * p);
                }
            // Publish completion of panel (b, y) with release semantics.
            __syncthreads();
            if (tid == 0) { __threadfence(); atomicAdd(&g_done[b * 8 + y], 1); }
        } else {
            const float* qb = g_q + (size_t)b * SS;
            float* ob = out + (size_t)b * SS * SS;

            // Fold q_i + q_j - acc into acc (L1-bypassing q loads)
            #pragma unroll
            for (int i = 0; i < 4; i++) {
                float qi0 = __ldcg(&qb[mrow + i * 16]);
                float qi1 = __ldcg(&qb[mrow + i * 16 + 8]);
                #pragma unroll
                for (int j = 0; j < 4; j++) {
                    int c = ncol + j * 8;
                    float qj0 = __ldcg(&qb[c]), qj1 = __ldcg(&qb[c + 1]);
                    acc[i][j][0] = qi0 + qj0 - acc[i][j][0];
                    acc[i][j][1] = qi0 + qj1 - acc[i][j][1];
                    acc[i][j][2] = qi1 + qj0 - acc[i][j][2];
                    acc[i][j][3] = qi1 + qj1 - acc[i][j][3];
                }
            }

            const bool mirror = (bi != bj);
            float* sm = (float*)smem;
            if (mirror) {
                __syncthreads();   // all warps done reading pipeline stages
                int rl = wm * 64 + lane / 4;
                int cl = wn * 32 + (lane % 4) * 2;
                #pragma unroll
                for (int i = 0; i < 4; i++)
                    #pragma unroll
                    for (int j = 0; j < 4; j++) {
                        int r0 = rl + i * 16, c = cl + j * 8;
                        sm[(c    ) * TPAD + r0    ] = acc[i][j][0];
                        sm[(c + 1) * TPAD + r0    ] = acc[i][j][1];
                        sm[(c    ) * TPAD + r0 + 8] = acc[i][j][2];
                        sm[(c + 1) * TPAD + r0 + 8] = acc[i][j][3];
                    }
            }

            // Direct write of block (bi, bj)
            #pragma unroll
            for (int i = 0; i < 4; i++)
                #pragma unroll
                for (int j = 0; j < 4; j++) {
                    int c = ncol + j * 8;
                    *(float2*)(ob + (size_t)(mrow + i * 16)     * SS + c) =
                        make_float2(acc[i][j][0], acc[i][j][1]);
                    *(float2*)(ob + (size_t)(mrow + i * 16 + 8) * SS + c) =
                        make_float2(acc[i][j][2], acc[i][j][3]);
                }

            if (mirror) {
                __syncthreads();
                #pragma unroll
                for (int it = 0; it < 16; it++) {
                    int idx = tid + it * 256;   // 0..4095
                    int tr  = idx >> 5;         // 0..127 (row of mirrored block)
                    int f4  = idx & 31;         // float4 index
                    float4 v = *(float4*)&sm[tr * TPAD + f4 * 4];
                    *(float4*)(ob + (size_t)(rowB0 + tr) * SS + rowA0 + f4 * 4) = v;
                }
            }
        }
    }
}

// ---------------------------------------------------------------------------
extern "C" void kernel_launch(void* const* d_in, const int* in_sizes, int n_in,
                              void* d_out, int out_size) {
    const float* batch = (const float*)d_in[0];   // (64, 1024, 768) fp32
    const float* proj  = (const float*)d_in[1];   // (768, 768) fp32
    float* out = (float*)d_out;                   // (64, 1024, 1024) fp32

    cudaFuncSetAttribute(k_work, cudaFuncAttributeMaxDynamicSharedMemorySize, SMEM_MM);

    k_conv<<<NB_CONV + NB_PREP, 256>>>(batch, proj);          // (1) convert + reset flags
    k_work<<<GRID_W, 256, SMEM_MM>>>(out, batch);             // (2) fused mm1+mm2 queue
}